// round 5
// baseline (speedup 1.0000x reference)
#include <cuda_runtime.h>
#include <math.h>

// Problem constants
#define Tn   2048      // B*S tokens
#define Hn   768       // hidden
#define FFn  3072      // feedforward
#define Sn   256
#define Bn   8
#define NHn  12
#define HDn  64
#define NEn  4
#define Lnum 2

// ---------------- device scratch (no allocations allowed) ----------------
// Kernels reference these symbols directly; the host never queries their
// addresses (keeps kernel_launch 100% kernel-launch-only).
__device__ float g_x   [Tn * Hn];
__device__ float g_h   [Tn * Hn];
__device__ float g_q   [Tn * Hn];
__device__ float g_k   [Tn * Hn];
__device__ float g_v   [Tn * Hn];
__device__ float g_x2  [Tn * Hn];
__device__ float g_ffn [Tn * FFn];
__device__ int   g_pos [Tn];
__device__ int   g_type[Tn];
__device__ int   g_cnt [NEn];
__device__ int   g_idx [NEn * Tn];

// ---------------- index prep: detect int32 vs int64 on the wire ----------
__global__ void k_prep(const void* __restrict__ pos, const void* __restrict__ typ) {
    __shared__ int s64p, s64t;
    if (threadIdx.x == 0) {
        const int* p32 = (const int*)pos;
        const int* t32 = (const int*)typ;
        int ap = 1, at = 1;
        for (int i = 1; i < 64; i += 2) { if (p32[i] != 0) { ap = 0; break; } }
        for (int i = 1; i < 64; i += 2) { if (t32[i] != 0) { at = 0; break; } }
        s64p = ap; s64t = at;
    }
    __syncthreads();
    for (int i = threadIdx.x; i < Tn; i += blockDim.x) {
        g_pos[i]  = s64p ? (int)((const long long*)pos)[i] : ((const int*)pos)[i];
        g_type[i] = s64t ? (int)((const long long*)typ)[i] : ((const int*)typ)[i];
    }
}

// ---------------- expert routing (order-independent result) --------------
__global__ void k_route() {
    __shared__ int cnt[NEn];
    if (threadIdx.x < NEn) cnt[threadIdx.x] = 0;
    __syncthreads();
    for (int i = threadIdx.x; i < Tn; i += blockDim.x) {
        int e = g_type[i];
        int p = atomicAdd(&cnt[e], 1);
        g_idx[e * Tn + p] = i;
    }
    __syncthreads();
    if (threadIdx.x < NEn) g_cnt[threadIdx.x] = cnt[threadIdx.x];
}

// ---------------- x = input + sinusoidal PE -------------------------------
__global__ void k_add_pe(const float* __restrict__ xin) {
    int row = blockIdx.x;
    int s = row % Sn;
    const float c = -logf(10000.0f) / (float)Hn;
    for (int d = threadIdx.x; d < Hn; d += blockDim.x) {
        int i2 = d & ~1;
        float ang = (float)s * expf((float)i2 * c);
        float pe = (d & 1) ? cosf(ang) : sinf(ang);
        g_x[(size_t)row * Hn + d] = xin[(size_t)row * Hn + d] + pe;
    }
}

// ---------------- layernorm: g_x -> g_h (row per block, 256 thr) ----------
__device__ __forceinline__ float warpSum(float v) {
#pragma unroll
    for (int o = 16; o > 0; o >>= 1) v += __shfl_down_sync(0xffffffffu, v, o);
    return v;
}

__global__ void __launch_bounds__(256) k_ln(const float* __restrict__ w,
                                            const float* __restrict__ b) {
    int row = blockIdx.x;
    int t = threadIdx.x;
    const float* x = g_x + (size_t)row * Hn;
    float v0 = x[t], v1 = x[t + 256], v2 = x[t + 512];
    __shared__ float red[8];
    float s = warpSum(v0 + v1 + v2);
    if ((t & 31) == 0) red[t >> 5] = s;
    __syncthreads();
    float tot = red[0]+red[1]+red[2]+red[3]+red[4]+red[5]+red[6]+red[7];
    float mu = tot * (1.0f / Hn);
    float d0 = v0 - mu, d1 = v1 - mu, d2 = v2 - mu;
    __syncthreads();
    s = warpSum(d0*d0 + d1*d1 + d2*d2);
    if ((t & 31) == 0) red[t >> 5] = s;
    __syncthreads();
    float var = (red[0]+red[1]+red[2]+red[3]+red[4]+red[5]+red[6]+red[7]) * (1.0f / Hn);
    float r = rsqrtf(var + 1e-5f);
    float* o = g_h + (size_t)row * Hn;
    o[t]       = d0 * r * w[t]       + b[t];
    o[t + 256] = d1 * r * w[t + 256] + b[t + 256];
    o[t + 512] = d2 * r * w[t + 512] + b[t + 512];
}

// ---------------- tiled SGEMM body: C[M,N] = A[M,K] @ B[K,N] + epilogue ---
// BM=64, BN=128, BK=8, 128 threads, 8x8 micro-tile.
// EXPERT: rows gathered via ridx, M given by caller.
// MODE 0: +bias. MODE 1: gelu(+bias). MODE 2: +bias + residual(g_x).
template<bool EXPERT, int MODE>
__device__ __forceinline__ void gemm_body(
        const float* __restrict__ A, const float* __restrict__ B,
        const float* __restrict__ bias,
        float* __restrict__ C, int M, int N, int K, const int* ridx) {
    int m0 = blockIdx.x * 64;
    if (m0 >= M) return;
    int n0 = blockIdx.y * 128;

    __shared__ __align__(16) float As[8][64];
    __shared__ __align__(16) float Bs[8][128];

    int tid = threadIdx.x;
    int arow = tid >> 1, akq = tid & 1;
    int am = m0 + arow;
    bool avalid = am < M;
    int ga = avalid ? (EXPERT ? ridx[am] : am) : (EXPERT ? ridx[0] : 0);
    const float* Ap = A + (size_t)ga * K + akq * 4;

    int bk0 = tid >> 5;            // 0..3
    int bc  = (tid & 31) * 4;      // 0..124
    const float* Bp = B + n0 + bc;

    int ty = tid >> 4, tx = tid & 15;
    float accv[8][8];
#pragma unroll
    for (int i = 0; i < 8; i++)
#pragma unroll
        for (int j = 0; j < 8; j++) accv[i][j] = 0.f;

    for (int k0 = 0; k0 < K; k0 += 8) {
        float4 av = avalid ? *(const float4*)(Ap + k0) : make_float4(0.f,0.f,0.f,0.f);
        float4 b0 = *(const float4*)(Bp + (size_t)(k0 + bk0) * N);
        float4 b1 = *(const float4*)(Bp + (size_t)(k0 + bk0 + 4) * N);
        __syncthreads();
        As[akq*4 + 0][arow] = av.x; As[akq*4 + 1][arow] = av.y;
        As[akq*4 + 2][arow] = av.z; As[akq*4 + 3][arow] = av.w;
        *(float4*)&Bs[bk0    ][bc] = b0;
        *(float4*)&Bs[bk0 + 4][bc] = b1;
        __syncthreads();
#pragma unroll
        for (int kk = 0; kk < 8; kk++) {
            float a[8], bb[8];
            *(float4*)(a)      = *(const float4*)&As[kk][ty*8];
            *(float4*)(a + 4)  = *(const float4*)&As[kk][ty*8 + 4];
            *(float4*)(bb)     = *(const float4*)&Bs[kk][tx*8];
            *(float4*)(bb + 4) = *(const float4*)&Bs[kk][tx*8 + 4];
#pragma unroll
            for (int i = 0; i < 8; i++)
#pragma unroll
                for (int j = 0; j < 8; j++)
                    accv[i][j] += a[i] * bb[j];
        }
    }

#pragma unroll
    for (int i = 0; i < 8; i++) {
        int rm = m0 + ty * 8 + i;
        if (rm >= M) continue;
        int cr = EXPERT ? ridx[rm] : rm;
        float* cp = C + (size_t)cr * N + n0 + tx * 8;
        const float* bp = bias + n0 + tx * 8;
        const float* rp = (MODE == 2) ? (g_x + (size_t)cr * N + n0 + tx * 8) : nullptr;
#pragma unroll
        for (int j = 0; j < 8; j++) {
            float v = accv[i][j] + bp[j];
            if (MODE == 1) v = 0.5f * v * (1.0f + erff(v * 0.70710678118f));
            if (MODE == 2) v += rp[j];
            cp[j] = v;
        }
    }
}

// Fused QKV: one launch, blockIdx.z selects {q,k,v}. A = g_h.
__global__ void __launch_bounds__(128) k_gemm_qkv(
        const float* __restrict__ Wq, const float* __restrict__ bq,
        const float* __restrict__ Wk, const float* __restrict__ bk,
        const float* __restrict__ Wv, const float* __restrict__ bv) {
    int z = blockIdx.z;
    const float* B    = (z == 0) ? Wq : (z == 1) ? Wk : Wv;
    const float* bias = (z == 0) ? bq : (z == 1) ? bk : bv;
    float*       C    = (z == 0) ? g_q : (z == 1) ? g_k : g_v;
    gemm_body<false, 0>(g_h, B, bias, C, Tn, Hn, Hn, nullptr);
}

// Expert FFN layer 1: g_h -> gelu -> g_ffn. blockIdx.z = expert.
__global__ void __launch_bounds__(128) k_gemm_ffn1(
        const float* __restrict__ W1, const float* __restrict__ b1) {
    int e = blockIdx.z;
    gemm_body<true, 1>(g_h, W1 + (size_t)e * Hn * FFn, b1 + (size_t)e * FFn,
                       g_ffn, g_cnt[e], FFn, Hn, g_idx + e * Tn);
}

// Expert FFN layer 2: g_ffn -> +bias +g_x residual -> g_x2.
__global__ void __launch_bounds__(128) k_gemm_ffn2(
        const float* __restrict__ W2, const float* __restrict__ b2) {
    int e = blockIdx.z;
    gemm_body<true, 2>(g_ffn, W2 + (size_t)e * FFn * Hn, b2 + (size_t)e * Hn,
                       g_x2, g_cnt[e], Hn, FFn, g_idx + e * Tn);
}

// ---------------- attention: block per (b,h), thread per query ------------
// scores = q.k (no 1/sqrt(d)), mask -1e4 on invalid keys, online softmax,
// residual add into g_x.
__global__ void __launch_bounds__(256) k_attn() {
    int b = blockIdx.x / NHn;
    int h = blockIdx.x % NHn;
    int t = threadIdx.x; // query index
    const float* qp = g_q + ((size_t)(b * Sn + t)) * Hn + h * HDn;
    float qr[HDn];
#pragma unroll
    for (int d = 0; d < HDn; d += 4) {
        float4 v4 = *(const float4*)(qp + d);
        qr[d] = v4.x; qr[d+1] = v4.y; qr[d+2] = v4.z; qr[d+3] = v4.w;
    }
    float acc[HDn];
#pragma unroll
    for (int d = 0; d < HDn; d++) acc[d] = 0.f;
    float mx = -3.0e38f, lsum = 0.f;

    __shared__ __align__(16) float Ks[32][HDn];
    __shared__ __align__(16) float Vs[32][HDn];
    __shared__ float madd[32];

    for (int c = 0; c < Sn / 32; c++) {
        __syncthreads();
#pragma unroll
        for (int r = 0; r < 2; r++) {
            int f = t + r * 256;         // 0..511 float4 slots
            int j = f >> 4;              // key 0..31
            int d4 = (f & 15) * 4;
            size_t gi = ((size_t)(b * Sn + c * 32 + j)) * Hn + h * HDn + d4;
            *(float4*)&Ks[j][d4] = *(const float4*)(g_k + gi);
            *(float4*)&Vs[j][d4] = *(const float4*)(g_v + gi);
        }
        if (t < 32) madd[t] = (g_pos[b * Sn + c * 32 + t] != 0) ? 0.f : -10000.0f;
        __syncthreads();

        float s[32];
        float cmx = -3.0e38f;
#pragma unroll
        for (int j = 0; j < 32; j++) {
            float dot = 0.f;
#pragma unroll
            for (int d = 0; d < HDn; d += 4) {
                float4 kv = *(const float4*)&Ks[j][d];
                dot += qr[d]*kv.x + qr[d+1]*kv.y + qr[d+2]*kv.z + qr[d+3]*kv.w;
            }
            s[j] = dot + madd[j];
            cmx = fmaxf(cmx, s[j]);
        }
        float nm = fmaxf(mx, cmx);
        float corr = expf(mx - nm);
        lsum *= corr;
#pragma unroll
        for (int d = 0; d < HDn; d++) acc[d] *= corr;
#pragma unroll
        for (int j = 0; j < 32; j++) {
            float p = expf(s[j] - nm);
            lsum += p;
#pragma unroll
            for (int d = 0; d < HDn; d += 4) {
                float4 vv = *(const float4*)&Vs[j][d];
                acc[d]   += p * vv.x; acc[d+1] += p * vv.y;
                acc[d+2] += p * vv.z; acc[d+3] += p * vv.w;
            }
        }
        mx = nm;
    }
    float inv = 1.0f / lsum;
    float* xp = g_x + ((size_t)(b * Sn + t)) * Hn + h * HDn;
#pragma unroll
    for (int d = 0; d < HDn; d++) xp[d] += acc[d] * inv;
}

// ---------------- end-of-layer permutation: dst[i] = g_x2[pos[i]-1] -------
// dst_out == nullptr -> write to g_x (intermediate layer), else to dst_out.
__global__ void k_scatter(float* __restrict__ dst_out) {
    int row = blockIdx.x;
    float* dst = dst_out ? dst_out : g_x;
    int p = g_pos[row];
    for (int d = threadIdx.x; d < Hn; d += blockDim.x)
        dst[(size_t)row * Hn + d] = (p > 0) ? g_x2[(size_t)(p - 1) * Hn + d] : 0.f;
}

// ---------------- launch: kernel launches ONLY ----------------------------
extern "C" void kernel_launch(void* const* d_in, const int* in_sizes, int n_in,
                              void* d_out, int out_size) {
    const float* x_in  = (const float*)d_in[0];
    const void*  npos  = d_in[1];
    const void*  ntype = d_in[2];
    const float* Wq  = (const float*)d_in[3];
    const float* bq  = (const float*)d_in[4];
    const float* Wk  = (const float*)d_in[5];
    const float* bk  = (const float*)d_in[6];
    const float* Wv  = (const float*)d_in[7];
    const float* bv  = (const float*)d_in[8];
    const float* ln1w = (const float*)d_in[9];
    const float* ln1b = (const float*)d_in[10];
    const float* ln2w = (const float*)d_in[11];
    const float* ln2b = (const float*)d_in[12];
    const float* W1 = (const float*)d_in[13];
    const float* b1 = (const float*)d_in[14];
    const float* W2 = (const float*)d_in[15];
    const float* b2 = (const float*)d_in[16];
    float* out = (float*)d_out;

    k_prep<<<1, 256>>>(npos, ntype);
    k_route<<<1, 256>>>();
    k_add_pe<<<Tn, 256>>>(x_in);

    for (int l = 0; l < Lnum; l++) {
        k_ln<<<Tn, 256>>>(ln1w + l * Hn, ln1b + l * Hn);

        k_gemm_qkv<<<dim3(Tn / 64, Hn / 128, 3), 128>>>(
            Wq + (size_t)l * Hn * Hn, bq + l * Hn,
            Wk + (size_t)l * Hn * Hn, bk + l * Hn,
            Wv + (size_t)l * Hn * Hn, bv + l * Hn);

        k_attn<<<Bn * NHn, 256>>>();

        k_ln<<<Tn, 256>>>(ln2w + l * Hn, ln2b + l * Hn);

        k_gemm_ffn1<<<dim3(Tn / 64, FFn / 128, NEn), 128>>>(
            W1 + (size_t)l * NEn * Hn * FFn, b1 + (size_t)l * NEn * FFn);

        k_gemm_ffn2<<<dim3(Tn / 64, Hn / 128, NEn), 128>>>(
            W2 + (size_t)l * NEn * FFn * Hn, b2 + (size_t)l * NEn * Hn);

        k_scatter<<<Tn, 256>>>((l == Lnum - 1) ? out : nullptr);
    }
}

// round 7
// speedup vs baseline: 2.4771x; 2.4771x over previous
#include <cuda_runtime.h>
#include <math.h>
#include <stdint.h>

// Problem constants
#define Tn   2048
#define Hn   768
#define FFn  3072
#define Sn   256
#define Bn   8
#define NHn  12
#define HDn  64
#define NEn  4
#define Lnum 2

// ---------------- device scratch ----------------
__device__ float g_x  [Tn * Hn];
__device__ float g_h  [Tn * Hn];     // LN1 out (token order)
__device__ float g_hg [Tn * Hn];     // LN2 out (expert-sorted order)
__device__ float g_q  [Tn * Hn];
__device__ float g_k  [Tn * Hn];
__device__ float g_v  [Tn * Hn];
__device__ float g_x2 [Tn * Hn];
__device__ float g_ffn[(size_t)Tn * FFn];  // FFN1 out (expert-sorted order)
__device__ int   g_pos [Tn];
__device__ int   g_type[Tn];
__device__ int   g_ord [Tn];         // expert-sorted -> token id
__device__ int   g_off [NEn + 1];    // expert prefix offsets

// ---------------- PTX helpers (sm_80-level PTX only, no 'a' features) -----
__device__ __forceinline__ uint32_t su32(const void* p) {
    uint32_t a;
    asm("{ .reg .u64 t; cvta.to.shared.u64 t, %1; cvt.u32.u64 %0, t; }"
        : "=r"(a) : "l"(p));
    return a;
}
__device__ __forceinline__ void cpa16(uint32_t dst, const void* src) {
    asm volatile("cp.async.cg.shared.global [%0], [%1], 16;" :: "r"(dst), "l"(src));
}
__device__ __forceinline__ void cpa_commit() {
    asm volatile("cp.async.commit_group;" ::: "memory");
}
__device__ __forceinline__ void cpa_wait1() {
    asm volatile("cp.async.wait_group 1;" ::: "memory");
}
__device__ __forceinline__ uint32_t f2tf32(float f) {
    uint32_t r;
    asm("cvt.rna.tf32.f32 %0, %1;" : "=r"(r) : "f"(f));
    return r;
}
__device__ __forceinline__ void mma_tf32(float* c, const uint32_t* a,
                                         uint32_t b0, uint32_t b1) {
    asm volatile(
        "mma.sync.aligned.m16n8k8.row.col.f32.tf32.tf32.f32 "
        "{%0,%1,%2,%3}, {%4,%5,%6,%7}, {%8,%9}, {%0,%1,%2,%3};"
        : "+f"(c[0]), "+f"(c[1]), "+f"(c[2]), "+f"(c[3])
        : "r"(a[0]), "r"(a[1]), "r"(a[2]), "r"(a[3]), "r"(b0), "r"(b1));
}

// ---------------- index prep ----------------
__global__ void k_prep(const void* __restrict__ pos, const void* __restrict__ typ) {
    __shared__ int s64p, s64t;
    if (threadIdx.x == 0) {
        const int* p32 = (const int*)pos;
        const int* t32 = (const int*)typ;
        int ap = 1, at = 1;
        for (int i = 1; i < 64; i += 2) { if (p32[i] != 0) { ap = 0; break; } }
        for (int i = 1; i < 64; i += 2) { if (t32[i] != 0) { at = 0; break; } }
        s64p = ap; s64t = at;
    }
    __syncthreads();
    for (int i = threadIdx.x; i < Tn; i += blockDim.x) {
        g_pos[i]  = s64p ? (int)((const long long*)pos)[i] : ((const int*)pos)[i];
        g_type[i] = s64t ? (int)((const long long*)typ)[i] : ((const int*)typ)[i];
    }
}

// ---------------- expert routing: counts, offsets, sorted order ----------
__global__ void k_route() {
    __shared__ int cnt[NEn], cur[NEn];
    int t = threadIdx.x;
    if (t < NEn) cnt[t] = 0;
    __syncthreads();
    for (int i = t; i < Tn; i += blockDim.x) atomicAdd(&cnt[g_type[i]], 1);
    __syncthreads();
    if (t == 0) {
        int run = 0;
        for (int e = 0; e < NEn; e++) { g_off[e] = run; cur[e] = run; run += cnt[e]; }
        g_off[NEn] = run;
    }
    __syncthreads();
    for (int i = t; i < Tn; i += blockDim.x) {
        int p = atomicAdd(&cur[g_type[i]], 1);
        g_ord[p] = i;
    }
}

// ---------------- x = input + sinusoidal PE ----------------
__global__ void k_add_pe(const float* __restrict__ xin) {
    int row = blockIdx.x;
    int s = row % Sn;
    const float c = -logf(10000.0f) / (float)Hn;
    for (int d = threadIdx.x; d < Hn; d += blockDim.x) {
        int i2 = d & ~1;
        float ang = (float)s * expf((float)i2 * c);
        float pe = (d & 1) ? cosf(ang) : sinf(ang);
        g_x[(size_t)row * Hn + d] = xin[(size_t)row * Hn + d] + pe;
    }
}

// ---------------- layernorm. GATHER=0: g_x->g_h; GATHER=1: g_x[ord]->g_hg --
__device__ __forceinline__ float warpSum(float v) {
#pragma unroll
    for (int o = 16; o > 0; o >>= 1) v += __shfl_down_sync(0xffffffffu, v, o);
    return v;
}
template<int GATHER>
__global__ void __launch_bounds__(256) k_ln(const float* __restrict__ w,
                                            const float* __restrict__ b) {
    int row = blockIdx.x;
    int rin = GATHER ? g_ord[row] : row;
    int t = threadIdx.x;
    const float* x = g_x + (size_t)rin * Hn;
    float v0 = x[t], v1 = x[t + 256], v2 = x[t + 512];
    __shared__ float red[8];
    float s = warpSum(v0 + v1 + v2);
    if ((t & 31) == 0) red[t >> 5] = s;
    __syncthreads();
    float tot = red[0]+red[1]+red[2]+red[3]+red[4]+red[5]+red[6]+red[7];
    float mu = tot * (1.0f / Hn);
    float d0 = v0 - mu, d1 = v1 - mu, d2 = v2 - mu;
    __syncthreads();
    s = warpSum(d0*d0 + d1*d1 + d2*d2);
    if ((t & 31) == 0) red[t >> 5] = s;
    __syncthreads();
    float var = (red[0]+red[1]+red[2]+red[3]+red[4]+red[5]+red[6]+red[7]) * (1.0f / Hn);
    float r = rsqrtf(var + 1e-5f);
    float* o = (GATHER ? g_hg : g_h) + (size_t)row * Hn;
    o[t]       = d0 * r * w[t]       + b[t];
    o[t + 256] = d1 * r * w[t + 256] + b[t + 256];
    o[t + 512] = d2 * r * w[t + 512] + b[t + 512];
}

// ---------------- tf32 mma.sync GEMM --------------------------------------
// C[M,N] = A[M,K] @ W[K,N] + epilogue.
// BM=128, BN=128, BK=32. 256 threads = 8 warps (4 M x 2 N), warp tile 32x64.
// mma m16n8k8 tf32, 3-stage cp.async pipeline.
// smem per stage: As[128][36] (pad->conflict-free frag reads),
//                 Bs[32][136]. stage = 35840 B, 3 stages = 107520 B.
// MODE 0: QKV  (A=g_h, z in {0,1,2} picks W/bias/out, M=Tn)
// MODE 1: FFN1 (A=g_hg rows off[z].., gelu, out g_ffn sorted rows)
// MODE 2: FFN2 (A=g_ffn sorted rows, +bias + g_x[tok] residual -> g_x2[tok])
#define LDA_S 36
#define LDB_S 136
#define STG_F 8960   // floats per stage (35840 B)

template<int MODE>
__global__ void __launch_bounds__(256) k_mm(
        const float* __restrict__ W0, const float* __restrict__ W1p,
        const float* __restrict__ W2p,
        const float* __restrict__ B0, const float* __restrict__ B1p,
        const float* __restrict__ B2p,
        int N, int K, int lda) {
    extern __shared__ float sm[];

    int z = blockIdx.z;
    const float* A; const float* W; const float* bias;
    int M, rowbase;
    if (MODE == 0) {
        A = g_h;
        W    = (z == 0) ? W0 : (z == 1) ? W1p : W2p;
        bias = (z == 0) ? B0 : (z == 1) ? B1p : B2p;
        M = Tn; rowbase = 0;
    } else {
        A = (MODE == 1) ? g_hg : g_ffn;
        W = W0 + (size_t)z * K * N;
        bias = B0 + (size_t)z * N;
        rowbase = g_off[z];
        M = g_off[z + 1] - rowbase;
    }
    int m0 = blockIdx.x * 128;
    if (m0 >= M) return;
    int n0 = blockIdx.y * 128;

    int tid = threadIdx.x;
    int wid = tid >> 5, lane = tid & 31;
    int gid = lane >> 2, tig = lane & 3;
    int wm = wid & 3, wn = wid >> 2;       // warp tile origin (wm*32, wn*64)
    int nch = K >> 5;

    uint32_t smb = su32(sm);

    float acc[2][8][4];
#pragma unroll
    for (int i = 0; i < 2; i++)
#pragma unroll
        for (int j = 0; j < 8; j++)
#pragma unroll
            for (int q = 0; q < 4; q++) acc[i][j][q] = 0.f;

    auto load_chunk = [&](int ci, int st) {
        uint32_t sA = smb + (uint32_t)st * (STG_F * 4);
        uint32_t sB = sA + 4608u * 4u;
        int k0 = ci << 5;
        // A: 128 rows x 32 floats -> As[r][c], stride 36
#pragma unroll
        for (int ii = 0; ii < 4; ii++) {
            int i = tid + ii * 256;
            int r = i >> 3, c = (i & 7) * 4;
            int gr = rowbase + min(m0 + r, M - 1);
            cpa16(sA + (uint32_t)(r * LDA_S + c) * 4u,
                  A + (size_t)gr * lda + k0 + c);
        }
        // B: 32 k-rows x 128 floats -> Bs[r][c], stride 136
#pragma unroll
        for (int ii = 0; ii < 4; ii++) {
            int i = tid + ii * 256;
            int r = i >> 5, c = (i & 31) * 4;
            cpa16(sB + (uint32_t)(r * LDB_S + c) * 4u,
                  W + (size_t)(k0 + r) * N + n0 + c);
        }
    };

    // prologue: 2 chunks in flight
    load_chunk(0, 0); cpa_commit();
    if (nch > 1) load_chunk(1, 1); cpa_commit();

    for (int i = 0; i < nch; i++) {
        cpa_wait1();            // chunk i resident
        __syncthreads();
        if (i + 2 < nch) load_chunk(i + 2, (i + 2) % 3);
        cpa_commit();           // exactly one group per iteration

        const float* sA = sm + (i % 3) * STG_F;
        const float* sB = sA + 4608;
#pragma unroll
        for (int kg = 0; kg < 4; kg++) {
            int kb = kg * 8;
            uint32_t a[2][4];
#pragma unroll
            for (int mi = 0; mi < 2; mi++) {
                int rm = wm * 32 + mi * 16 + gid;
                a[mi][0] = f2tf32(sA[rm * LDA_S + kb + tig]);
                a[mi][1] = f2tf32(sA[(rm + 8) * LDA_S + kb + tig]);
                a[mi][2] = f2tf32(sA[rm * LDA_S + kb + tig + 4]);
                a[mi][3] = f2tf32(sA[(rm + 8) * LDA_S + kb + tig + 4]);
            }
#pragma unroll
            for (int ni = 0; ni < 8; ni++) {
                int cn = wn * 64 + ni * 8 + gid;
                uint32_t b0 = f2tf32(sB[(kb + tig) * LDB_S + cn]);
                uint32_t b1 = f2tf32(sB[(kb + tig + 4) * LDB_S + cn]);
                mma_tf32(acc[0][ni], a[0], b0, b1);
                mma_tf32(acc[1][ni], a[1], b0, b1);
            }
        }
        __syncthreads();
    }

    // ---------------- epilogue ----------------
    float* Optr;
    if (MODE == 0)      Optr = (z == 0) ? g_q : (z == 1) ? g_k : g_v;
    else if (MODE == 1) Optr = g_ffn;
    else                Optr = g_x2;

#pragma unroll
    for (int mi = 0; mi < 2; mi++) {
#pragma unroll
        for (int half = 0; half < 2; half++) {
            int rl = m0 + wm * 32 + mi * 16 + half * 8 + gid;
            if (rl >= M) continue;
            int orow;
            if (MODE == 0)      orow = rl;
            else if (MODE == 1) orow = rowbase + rl;
            else                orow = g_ord[rowbase + rl];
            float* orp = Optr + (size_t)orow * N;
            const float* rx = g_x + (size_t)orow * Hn;   // MODE 2 residual
#pragma unroll
            for (int ni = 0; ni < 8; ni++) {
                int col = n0 + wn * 64 + ni * 8 + tig * 2;
                float2 bv = *(const float2*)(bias + col);
                float vx = acc[mi][ni][half * 2 + 0] + bv.x;
                float vy = acc[mi][ni][half * 2 + 1] + bv.y;
                if (MODE == 1) {
                    vx = 0.5f * vx * (1.0f + erff(vx * 0.70710678118f));
                    vy = 0.5f * vy * (1.0f + erff(vy * 0.70710678118f));
                }
                if (MODE == 2) {
                    float2 xr = *(const float2*)(rx + col);
                    vx += xr.x; vy += xr.y;
                }
                float2 o2 = make_float2(vx, vy);
                *(float2*)(orp + col) = o2;
            }
        }
    }
}

// ---------------- attention: block per (b,h,qchunk of 64), fp32 ----------
__global__ void __launch_bounds__(64) k_attn() {
    int b = blockIdx.x / NHn;
    int h = blockIdx.x % NHn;
    int t = blockIdx.y * 64 + threadIdx.x;   // query index
    int tid = threadIdx.x;
    const float* qp = g_q + ((size_t)(b * Sn + t)) * Hn + h * HDn;
    float qr[HDn];
#pragma unroll
    for (int d = 0; d < HDn; d += 4) {
        float4 v4 = *(const float4*)(qp + d);
        qr[d] = v4.x; qr[d+1] = v4.y; qr[d+2] = v4.z; qr[d+3] = v4.w;
    }
    float acc[HDn];
#pragma unroll
    for (int d = 0; d < HDn; d++) acc[d] = 0.f;
    float mx = -3.0e38f, lsum = 0.f;

    __shared__ __align__(16) float Ks[32][HDn];
    __shared__ __align__(16) float Vs[32][HDn];
    __shared__ float madd[32];

    for (int c = 0; c < Sn / 32; c++) {
        __syncthreads();
        for (int i = tid; i < 512; i += 64) {     // 32 keys x 16 float4
            int j = i >> 4, d4 = (i & 15) * 4;
            size_t gi = ((size_t)(b * Sn + c * 32 + j)) * Hn + h * HDn + d4;
            *(float4*)&Ks[j][d4] = *(const float4*)(g_k + gi);
            *(float4*)&Vs[j][d4] = *(const float4*)(g_v + gi);
        }
        if (tid < 32) madd[tid] = (g_pos[b * Sn + c * 32 + tid] != 0) ? 0.f : -10000.0f;
        __syncthreads();

        float s[32];
        float cmx = -3.0e38f;
#pragma unroll
        for (int j = 0; j < 32; j++) {
            float dot = 0.f;
#pragma unroll
            for (int d = 0; d < HDn; d += 4) {
                float4 kv = *(const float4*)&Ks[j][d];
                dot += qr[d]*kv.x + qr[d+1]*kv.y + qr[d+2]*kv.z + qr[d+3]*kv.w;
            }
            s[j] = dot + madd[j];
            cmx = fmaxf(cmx, s[j]);
        }
        float nm = fmaxf(mx, cmx);
        float corr = expf(mx - nm);
        lsum *= corr;
#pragma unroll
        for (int d = 0; d < HDn; d++) acc[d] *= corr;
#pragma unroll
        for (int j = 0; j < 32; j++) {
            float p = expf(s[j] - nm);
            lsum += p;
#pragma unroll
            for (int d = 0; d < HDn; d += 4) {
                float4 vv = *(const float4*)&Vs[j][d];
                acc[d]   += p * vv.x; acc[d+1] += p * vv.y;
                acc[d+2] += p * vv.z; acc[d+3] += p * vv.w;
            }
        }
        mx = nm;
    }
    float inv = 1.0f / lsum;
    float* xp = g_x + ((size_t)(b * Sn + t)) * Hn + h * HDn;
#pragma unroll
    for (int d = 0; d < HDn; d++) xp[d] += acc[d] * inv;
}

// ---------------- end-of-layer permutation: dst[i] = g_x2[pos[i]-1] -------
__global__ void k_scatter(float* __restrict__ dst_out) {
    int row = blockIdx.x;
    float* dst = dst_out ? dst_out : g_x;
    int p = g_pos[row];
    for (int d = threadIdx.x; d < Hn; d += blockDim.x)
        dst[(size_t)row * Hn + d] = (p > 0) ? g_x2[(size_t)(p - 1) * Hn + d] : 0.f;
}

// ---------------- launch ---------------------------------------------------
extern "C" void kernel_launch(void* const* d_in, const int* in_sizes, int n_in,
                              void* d_out, int out_size) {
    const float* x_in  = (const float*)d_in[0];
    const void*  npos  = d_in[1];
    const void*  ntype = d_in[2];
    const float* Wq  = (const float*)d_in[3];
    const float* bq  = (const float*)d_in[4];
    const float* Wk  = (const float*)d_in[5];
    const float* bk  = (const float*)d_in[6];
    const float* Wv  = (const float*)d_in[7];
    const float* bv  = (const float*)d_in[8];
    const float* ln1w = (const float*)d_in[9];
    const float* ln1b = (const float*)d_in[10];
    const float* ln2w = (const float*)d_in[11];
    const float* ln2b = (const float*)d_in[12];
    const float* W1 = (const float*)d_in[13];
    const float* b1 = (const float*)d_in[14];
    const float* W2 = (const float*)d_in[15];
    const float* b2 = (const float*)d_in[16];
    float* out = (float*)d_out;

    const int SMEM = 3 * STG_F * 4;   // 107520 B
    static int attr_done = 0;
    if (!attr_done) {
        cudaFuncSetAttribute(k_mm<0>, cudaFuncAttributeMaxDynamicSharedMemorySize, SMEM);
        cudaFuncSetAttribute(k_mm<1>, cudaFuncAttributeMaxDynamicSharedMemorySize, SMEM);
        cudaFuncSetAttribute(k_mm<2>, cudaFuncAttributeMaxDynamicSharedMemorySize, SMEM);
        attr_done = 1;
    }

    k_prep<<<1, 256>>>(npos, ntype);
    k_route<<<1, 256>>>();
    k_add_pe<<<Tn, 256>>>(x_in);

    for (int l = 0; l < Lnum; l++) {
        k_ln<0><<<Tn, 256>>>(ln1w + l * Hn, ln1b + l * Hn);

        k_mm<0><<<dim3(Tn / 128, Hn / 128, 3), 256, SMEM>>>(
            Wq + (size_t)l * Hn * Hn, Wk + (size_t)l * Hn * Hn,
            Wv + (size_t)l * Hn * Hn,
            bq + l * Hn, bk + l * Hn, bv + l * Hn,
            Hn, Hn, Hn);

        k_attn<<<dim3(Bn * NHn, Sn / 64), 64>>>();

        k_ln<1><<<Tn, 256>>>(ln2w + l * Hn, ln2b + l * Hn);

        k_mm<1><<<dim3(Tn / 128, FFn / 128, NEn), 256, SMEM>>>(
            W1 + (size_t)l * NEn * Hn * FFn, nullptr, nullptr,
            b1 + (size_t)l * NEn * FFn, nullptr, nullptr,
            FFn, Hn, Hn);

        k_mm<2><<<dim3(Tn / 128, Hn / 128, NEn), 256, SMEM>>>(
            W2 + (size_t)l * NEn * FFn * Hn, nullptr, nullptr,
            b2 + (size_t)l * NEn * Hn, nullptr, nullptr,
            Hn, FFn, FFn);

        k_scatter<<<Tn, 256>>>((l == Lnum - 1) ? out : nullptr);
    }
}

// round 9
// speedup vs baseline: 3.4873x; 1.4078x over previous
#include <cuda_runtime.h>
#include <cuda_fp16.h>
#include <math.h>
#include <stdint.h>

// Problem constants
#define Tn   2048
#define Hn   768
#define FFn  3072
#define Sn   256
#define Bn   8
#define NHn  12
#define HDn  64
#define NEn  4
#define Lnum 2

// Weight fp16 region offsets (in half2 units)
#define WQ_OFF  0
#define WK_OFF  589824
#define WV_OFF  1179648
#define W1_OFF  1769472
#define W2_OFF  11206656
#define W16_TOT 20643840

// ---------------- device scratch ----------------
__device__ float  g_x   [Tn * Hn];
__device__ __half g_h16 [Tn * Hn];
__device__ __half g_hg16[Tn * Hn];
__device__ float  g_q   [Tn * Hn];
__device__ float  g_k   [Tn * Hn];
__device__ float  g_v   [Tn * Hn];
__device__ float  g_x2  [Tn * Hn];
__device__ __half g_ffn16[(size_t)Tn * FFn];
__device__ float  g_part[3 * Tn * Hn];
__device__ __half g_w16 [2 * W16_TOT];   // half count = 2 * h2 count
__device__ int    g_pos [Tn];
__device__ int    g_type[Tn];
__device__ int    g_ord [Tn];
__device__ int    g_off [NEn + 1];

// ---------------- PTX helpers ----------------
__device__ __forceinline__ uint32_t su32(const void* p) {
    uint32_t a;
    asm("{ .reg .u64 t; cvta.to.shared.u64 t, %1; cvt.u32.u64 %0, t; }"
        : "=r"(a) : "l"(p));
    return a;
}
__device__ __forceinline__ void cpa16(uint32_t dst, const void* src) {
    asm volatile("cp.async.cg.shared.global [%0], [%1], 16;" :: "r"(dst), "l"(src));
}
__device__ __forceinline__ void cpa_commit() {
    asm volatile("cp.async.commit_group;" ::: "memory");
}
__device__ __forceinline__ void cpa_wait1() {
    asm volatile("cp.async.wait_group 1;" ::: "memory");
}
__device__ __forceinline__ void mma_f16(float* c, const uint32_t* a,
                                        uint32_t b0, uint32_t b1) {
    asm volatile(
        "mma.sync.aligned.m16n8k16.row.col.f32.f16.f16.f32 "
        "{%0,%1,%2,%3}, {%4,%5,%6,%7}, {%8,%9}, {%0,%1,%2,%3};"
        : "+f"(c[0]), "+f"(c[1]), "+f"(c[2]), "+f"(c[3])
        : "r"(a[0]), "r"(a[1]), "r"(a[2]), "r"(a[3]), "r"(b0), "r"(b1));
}

// ---------------- weight fp32 -> fp16 (k-pair interleaved half2) ----------
// dst[m][k2][n] = half2(W[m][2k2][n], W[m][2k2+1][n])
__global__ void k_cvtw(const float* __restrict__ src, int dsth2,
                       int K, int N, long total) {
    __half2* dst = ((__half2*)(void*)g_w16) + dsth2;
    long K2N = (long)(K / 2) * N;
    for (long i = (long)blockIdx.x * blockDim.x + threadIdx.x; i < total;
         i += (long)gridDim.x * blockDim.x) {
        long m = i / K2N;
        long r = i - m * K2N;
        int k2 = (int)(r / N), n = (int)(r - (long)k2 * N);
        const float* s = src + m * K * N + (size_t)(2 * k2) * N + n;
        dst[i] = __floats2half2_rn(s[0], s[N]);
    }
}

// ---------------- index prep ----------------
__global__ void k_prep(const void* __restrict__ pos, const void* __restrict__ typ) {
    __shared__ int s64p, s64t;
    if (threadIdx.x == 0) {
        const int* p32 = (const int*)pos;
        const int* t32 = (const int*)typ;
        int ap = 1, at = 1;
        for (int i = 1; i < 64; i += 2) { if (p32[i] != 0) { ap = 0; break; } }
        for (int i = 1; i < 64; i += 2) { if (t32[i] != 0) { at = 0; break; } }
        s64p = ap; s64t = at;
    }
    __syncthreads();
    for (int i = threadIdx.x; i < Tn; i += blockDim.x) {
        g_pos[i]  = s64p ? (int)((const long long*)pos)[i] : ((const int*)pos)[i];
        g_type[i] = s64t ? (int)((const long long*)typ)[i] : ((const int*)typ)[i];
    }
}

// ---------------- expert routing ----------------
__global__ void k_route() {
    __shared__ int cnt[NEn], cur[NEn];
    int t = threadIdx.x;
    if (t < NEn) cnt[t] = 0;
    __syncthreads();
    for (int i = t; i < Tn; i += blockDim.x) atomicAdd(&cnt[g_type[i]], 1);
    __syncthreads();
    if (t == 0) {
        int run = 0;
        for (int e = 0; e < NEn; e++) { g_off[e] = run; cur[e] = run; run += cnt[e]; }
        g_off[NEn] = run;
    }
    __syncthreads();
    for (int i = t; i < Tn; i += blockDim.x) {
        int p = atomicAdd(&cur[g_type[i]], 1);
        g_ord[p] = i;
    }
}

// ---------------- x = input + sinusoidal PE ----------------
__global__ void k_add_pe(const float* __restrict__ xin) {
    int row = blockIdx.x;
    int s = row % Sn;
    const float c = -logf(10000.0f) / (float)Hn;
    for (int d = threadIdx.x; d < Hn; d += blockDim.x) {
        int i2 = d & ~1;
        float ang = (float)s * expf((float)i2 * c);
        float pe = (d & 1) ? cosf(ang) : sinf(ang);
        g_x[(size_t)row * Hn + d] = xin[(size_t)row * Hn + d] + pe;
    }
}

// ---------------- layernorm -> fp16. GATHER picks in-row + out buffer -----
__device__ __forceinline__ float warpSum(float v) {
#pragma unroll
    for (int o = 16; o > 0; o >>= 1) v += __shfl_down_sync(0xffffffffu, v, o);
    return v;
}
template<int GATHER>
__global__ void __launch_bounds__(192) k_ln(const float* __restrict__ w,
                                            const float* __restrict__ b) {
    int row = blockIdx.x;
    int rin = GATHER ? g_ord[row] : row;
    int t = threadIdx.x;
    float4 v = ((const float4*)(g_x + (size_t)rin * Hn))[t];
    __shared__ float red[6];
    float s = warpSum(v.x + v.y + v.z + v.w);
    if ((t & 31) == 0) red[t >> 5] = s;
    __syncthreads();
    float mu = (red[0]+red[1]+red[2]+red[3]+red[4]+red[5]) * (1.0f / Hn);
    float4 d = make_float4(v.x - mu, v.y - mu, v.z - mu, v.w - mu);
    __syncthreads();
    s = warpSum(d.x*d.x + d.y*d.y + d.z*d.z + d.w*d.w);
    if ((t & 31) == 0) red[t >> 5] = s;
    __syncthreads();
    float var = (red[0]+red[1]+red[2]+red[3]+red[4]+red[5]) * (1.0f / Hn);
    float r = rsqrtf(var + 1e-5f);
    float4 wv = ((const float4*)w)[t];
    float4 bv = ((const float4*)b)[t];
    __half2* o = (__half2*)((GATHER ? g_hg16 : g_h16) + (size_t)row * Hn);
    o[t * 2]     = __floats2half2_rn(d.x * r * wv.x + bv.x, d.y * r * wv.y + bv.y);
    o[t * 2 + 1] = __floats2half2_rn(d.z * r * wv.z + bv.z, d.w * r * wv.w + bv.w);
}

// ---------------- fp16 mma GEMM -------------------------------------------
// BM=128, BN=256, BK=32 (16 half2). 256 threads = 8 warps (2M x 4N),
// warp tile 64x64, mma m16n8k16, 3-stage cp.async.
// smem (half2/u32 units): A 128x20, B 16x264 -> stage 6784 u32 = 27136 B.
// MODE 0: QKV (A=g_h16, z={q,k,v}, out fp32 g_q/g_k/g_v)
// MODE 1: FFN1 (A=g_hg16 expert rows, gelu, out half g_ffn16)
// MODE 2: FFN2 split-K (A=g_ffn16, z=(s<<2)|e, raw partial to g_part[s])
#define STG_U 6784

template<int MODE>
__global__ void __launch_bounds__(256) k_mm(int woff_l,
        const float* __restrict__ bq, const float* __restrict__ bk,
        const float* __restrict__ bv) {
    constexpr int N_    = (MODE == 1) ? FFn : Hn;
    constexpr int LDA2_ = (MODE == 2) ? (FFn / 2) : (Hn / 2);
    constexpr int NCH_  = (MODE == 2) ? 32 : 24;
    extern __shared__ uint32_t smu[];

    int z = blockIdx.z;
    int e = 0, sp = 0;
    int woff;
    const float* bias = nullptr;
    if (MODE == 0) {
        woff = woff_l + z * 589824;
        bias = (z == 0) ? bq : (z == 1) ? bk : bv;
    } else if (MODE == 1) {
        woff = woff_l + z * 1179648;
        bias = bq + z * FFn;
        e = z;
    } else {
        e = z & 3; sp = z >> 2;
        woff = woff_l + e * 1179648 + sp * 393216;
    }

    int M, rowbase;
    const __half2* A2;
    if (MODE == 0) { M = Tn; rowbase = 0; A2 = (const __half2*)(void*)g_h16; }
    else {
        rowbase = g_off[e];
        M = g_off[e + 1] - rowbase;
        A2 = (const __half2*)(void*)((MODE == 1) ? g_hg16 : g_ffn16);
    }
    int m0 = blockIdx.x * 128;
    if (m0 >= M) return;
    int n0 = blockIdx.y * 256;

    const __half2* W2g = ((const __half2*)(void*)g_w16) + woff;

    int tid = threadIdx.x;
    int wid = tid >> 5, lane = tid & 31;
    int gid = lane >> 2, tig = lane & 3;
    int wm = wid >> 2, wn = wid & 3;     // warp origin (wm*64, wn*64)

    uint32_t smb = su32(smu);

    float acc[4][8][4];
#pragma unroll
    for (int i = 0; i < 4; i++)
#pragma unroll
        for (int j = 0; j < 8; j++)
#pragma unroll
            for (int q = 0; q < 4; q++) acc[i][j][q] = 0.f;

    auto load_chunk = [&](int ci, int st) {
        uint32_t sA = smb + (uint32_t)st * (STG_U * 4);
        uint32_t sB = sA + 2560u * 4u;
        int ak2 = ci * 16 + ((MODE == 2) ? sp * 512 : 0);
        // A: 128 rows x 16 half2
#pragma unroll
        for (int ii = 0; ii < 2; ii++) {
            int i = tid + ii * 256;
            int r = i >> 2, cq = (i & 3) * 4;
            int gr = rowbase + ((MODE == 0) ? (m0 + r) : min(m0 + r, M - 1));
            cpa16(sA + (uint32_t)(r * 20 + cq) * 4u,
                  A2 + (size_t)gr * LDA2_ + ak2 + cq);
        }
        // B: 16 k2-rows x 256 cols half2
#pragma unroll
        for (int ii = 0; ii < 4; ii++) {
            int i = tid + ii * 256;
            int r = i >> 6, c = (i & 63) * 4;
            cpa16(sB + (uint32_t)(r * 264 + c) * 4u,
                  W2g + (size_t)(ci * 16 + r) * N_ + n0 + c);
        }
    };

    load_chunk(0, 0); cpa_commit();
    load_chunk(1, 1); cpa_commit();

    for (int i = 0; i < NCH_; i++) {
        cpa_wait1();
        __syncthreads();
        if (i + 2 < NCH_) load_chunk(i + 2, (i + 2) % 3);
        cpa_commit();

        const uint32_t* sAp = smu + (i % 3) * STG_U;
        const uint32_t* sBp = sAp + 2560;
#pragma unroll
        for (int kg = 0; kg < 2; kg++) {
            int kb2 = kg * 8;
            uint32_t a[4][4];
#pragma unroll
            for (int mi = 0; mi < 4; mi++) {
                int rm = wm * 64 + mi * 16 + gid;
                a[mi][0] = sAp[rm * 20 + kb2 + tig];
                a[mi][1] = sAp[(rm + 8) * 20 + kb2 + tig];
                a[mi][2] = sAp[rm * 20 + kb2 + tig + 4];
                a[mi][3] = sAp[(rm + 8) * 20 + kb2 + tig + 4];
            }
#pragma unroll
            for (int ni = 0; ni < 8; ni++) {
                int cn = wn * 64 + ni * 8 + gid;
                uint32_t b0 = sBp[(kb2 + tig) * 264 + cn];
                uint32_t b1 = sBp[(kb2 + tig + 4) * 264 + cn];
#pragma unroll
                for (int mi = 0; mi < 4; mi++)
                    mma_f16(acc[mi][ni], a[mi], b0, b1);
            }
        }
        __syncthreads();
    }

    // ---------------- epilogue ----------------
#pragma unroll
    for (int mi = 0; mi < 4; mi++) {
#pragma unroll
        for (int half = 0; half < 2; half++) {
            int rl = m0 + wm * 64 + mi * 16 + half * 8 + gid;
            if (rl >= M) continue;
#pragma unroll
            for (int ni = 0; ni < 8; ni++) {
                int col = n0 + wn * 64 + ni * 8 + tig * 2;
                float vx = acc[mi][ni][half * 2 + 0];
                float vy = acc[mi][ni][half * 2 + 1];
                if (MODE == 0) {
                    float2 bb = *(const float2*)(bias + col);
                    vx += bb.x; vy += bb.y;
                    float* Optr = (z == 0) ? g_q : (z == 1) ? g_k : g_v;
                    *(float2*)(Optr + (size_t)rl * Hn + col) = make_float2(vx, vy);
                } else if (MODE == 1) {
                    float2 bb = *(const float2*)(bias + col);
                    vx += bb.x; vy += bb.y;
                    vx = 0.5f * vx * (1.0f + erff(vx * 0.70710678118f));
                    vy = 0.5f * vy * (1.0f + erff(vy * 0.70710678118f));
                    int srow = rowbase + rl;
                    *(__half2*)(g_ffn16 + (size_t)srow * FFn + col) =
                        __floats2half2_rn(vx, vy);
                } else {
                    int srow = rowbase + rl;
                    *(float2*)(g_part + (size_t)sp * (Tn * Hn)
                               + (size_t)srow * Hn + col) = make_float2(vx, vy);
                }
            }
        }
    }
}

// ---------------- FFN2 finish: sum partials + bias + residual, unsort -----
__global__ void __launch_bounds__(192) k_fin(const float* __restrict__ b2l) {
    int rs = blockIdx.x;
    int t = threadIdx.x;
    __shared__ int se, so;
    if (t == 0) {
        int e = 0;
        while (!(rs >= g_off[e] && rs < g_off[e + 1])) e++;
        se = e; so = g_ord[rs];
    }
    __syncthreads();
    int e = se, orow = so;
    float4 p0 = ((const float4*)(g_part + 0 * (Tn * Hn) + (size_t)rs * Hn))[t];
    float4 p1 = ((const float4*)(g_part + 1 * (Tn * Hn) + (size_t)rs * Hn))[t];
    float4 p2 = ((const float4*)(g_part + 2 * (Tn * Hn) + (size_t)rs * Hn))[t];
    float4 bb = ((const float4*)(b2l + (size_t)e * Hn))[t];
    float4 xr = ((const float4*)(g_x + (size_t)orow * Hn))[t];
    float4 o;
    o.x = p0.x + p1.x + p2.x + bb.x + xr.x;
    o.y = p0.y + p1.y + p2.y + bb.y + xr.y;
    o.z = p0.z + p1.z + p2.z + bb.z + xr.z;
    o.w = p0.w + p1.w + p2.w + bb.w + xr.w;
    ((float4*)(g_x2 + (size_t)orow * Hn))[t] = o;
}

// ---------------- attention: block per (b,h,qchunk of 128), fp32 ----------
__global__ void __launch_bounds__(128) k_attn() {
    int b = blockIdx.x / NHn;
    int h = blockIdx.x % NHn;
    int t = blockIdx.y * 128 + threadIdx.x;   // query index
    int tid = threadIdx.x;
    const float* qp = g_q + ((size_t)(b * Sn + t)) * Hn + h * HDn;
    float qr[HDn];
#pragma unroll
    for (int d = 0; d < HDn; d += 4) {
        float4 v4 = *(const float4*)(qp + d);
        qr[d] = v4.x; qr[d+1] = v4.y; qr[d+2] = v4.z; qr[d+3] = v4.w;
    }
    float acc[HDn];
#pragma unroll
    for (int d = 0; d < HDn; d++) acc[d] = 0.f;
    float mx = -3.0e38f, lsum = 0.f;

    __shared__ __align__(16) float Ks[32][HDn];
    __shared__ __align__(16) float Vs[32][HDn];
    __shared__ float madd[32];

    for (int c = 0; c < Sn / 32; c++) {
        __syncthreads();
        for (int i = tid; i < 512; i += 128) {     // 32 keys x 16 float4
            int j = i >> 4, d4 = (i & 15) * 4;
            size_t gi = ((size_t)(b * Sn + c * 32 + j)) * Hn + h * HDn + d4;
            *(float4*)&Ks[j][d4] = *(const float4*)(g_k + gi);
            *(float4*)&Vs[j][d4] = *(const float4*)(g_v + gi);
        }
        if (tid < 32) madd[tid] = (g_pos[b * Sn + c * 32 + tid] != 0) ? 0.f : -10000.0f;
        __syncthreads();

        float s[32];
        float cmx = -3.0e38f;
#pragma unroll
        for (int j = 0; j < 32; j++) {
            float dot = 0.f;
#pragma unroll
            for (int d = 0; d < HDn; d += 4) {
                float4 kv = *(const float4*)&Ks[j][d];
                dot += qr[d]*kv.x + qr[d+1]*kv.y + qr[d+2]*kv.z + qr[d+3]*kv.w;
            }
            s[j] = dot + madd[j];
            cmx = fmaxf(cmx, s[j]);
        }
        float nm = fmaxf(mx, cmx);
        float corr = expf(mx - nm);
        lsum *= corr;
#pragma unroll
        for (int d = 0; d < HDn; d++) acc[d] *= corr;
#pragma unroll
        for (int j = 0; j < 32; j++) {
            float p = expf(s[j] - nm);
            lsum += p;
#pragma unroll
            for (int d = 0; d < HDn; d += 4) {
                float4 vv = *(const float4*)&Vs[j][d];
                acc[d]   += p * vv.x; acc[d+1] += p * vv.y;
                acc[d+2] += p * vv.z; acc[d+3] += p * vv.w;
            }
        }
        mx = nm;
    }
    float inv = 1.0f / lsum;
    float* xp = g_x + ((size_t)(b * Sn + t)) * Hn + h * HDn;
#pragma unroll
    for (int d = 0; d < HDn; d++) xp[d] += acc[d] * inv;
}

// ---------------- end-of-layer permutation: dst[i] = g_x2[pos[i]-1] -------
__global__ void k_scatter(float* __restrict__ dst_out) {
    int row = blockIdx.x;
    float* dst = dst_out ? dst_out : g_x;
    int p = g_pos[row];
    for (int d = threadIdx.x; d < Hn; d += blockDim.x)
        dst[(size_t)row * Hn + d] = (p > 0) ? g_x2[(size_t)(p - 1) * Hn + d] : 0.f;
}

// ---------------- launch ---------------------------------------------------
extern "C" void kernel_launch(void* const* d_in, const int* in_sizes, int n_in,
                              void* d_out, int out_size) {
    const float* x_in  = (const float*)d_in[0];
    const void*  npos  = d_in[1];
    const void*  ntype = d_in[2];
    const float* Wq  = (const float*)d_in[3];
    const float* bq  = (const float*)d_in[4];
    const float* Wk  = (const float*)d_in[5];
    const float* bk  = (const float*)d_in[6];
    const float* Wv  = (const float*)d_in[7];
    const float* bv  = (const float*)d_in[8];
    const float* ln1w = (const float*)d_in[9];
    const float* ln1b = (const float*)d_in[10];
    const float* ln2w = (const float*)d_in[11];
    const float* ln2b = (const float*)d_in[12];
    const float* W1 = (const float*)d_in[13];
    const float* b1 = (const float*)d_in[14];
    const float* W2 = (const float*)d_in[15];
    const float* b2 = (const float*)d_in[16];
    float* out = (float*)d_out;

    const int SMEM = 3 * STG_U * 4;   // 81408 B
    cudaFuncSetAttribute(k_mm<0>, cudaFuncAttributeMaxDynamicSharedMemorySize, SMEM);
    cudaFuncSetAttribute(k_mm<1>, cudaFuncAttributeMaxDynamicSharedMemorySize, SMEM);
    cudaFuncSetAttribute(k_mm<2>, cudaFuncAttributeMaxDynamicSharedMemorySize, SMEM);

    // Weight conversion to interleaved fp16 (every launch; deterministic)
    k_cvtw<<<1024, 256>>>(Wq, WQ_OFF, Hn, Hn, 2L * 294912);
    k_cvtw<<<1024, 256>>>(Wk, WK_OFF, Hn, Hn, 2L * 294912);
    k_cvtw<<<1024, 256>>>(Wv, WV_OFF, Hn, Hn, 2L * 294912);
    k_cvtw<<<2048, 256>>>(W1, W1_OFF, Hn, FFn, 8L * 1179648);
    k_cvtw<<<2048, 256>>>(W2, W2_OFF, FFn, Hn, 8L * 1179648);

    k_prep<<<1, 256>>>(npos, ntype);
    k_route<<<1, 256>>>();
    k_add_pe<<<Tn, 256>>>(x_in);

    for (int l = 0; l < Lnum; l++) {
        k_ln<0><<<Tn, 192>>>(ln1w + l * Hn, ln1b + l * Hn);

        k_mm<0><<<dim3(16, 3, 3), 256, SMEM>>>(
            l * 294912, bq + l * Hn, bk + l * Hn, bv + l * Hn);

        k_attn<<<dim3(Bn * NHn, Sn / 128), 128>>>();

        k_ln<1><<<Tn, 192>>>(ln2w + l * Hn, ln2b + l * Hn);

        k_mm<1><<<dim3(16, 12, 4), 256, SMEM>>>(
            W1_OFF + l * 4 * 1179648, b1 + (size_t)l * NEn * FFn, nullptr, nullptr);

        k_mm<2><<<dim3(16, 3, 12), 256, SMEM>>>(
            W2_OFF + l * 4 * 1179648, nullptr, nullptr, nullptr);

        k_fin<<<Tn, 192>>>(b2 + (size_t)l * NEn * Hn);

        k_scatter<<<Tn, 256>>>((l == Lnum - 1) ? out : nullptr);
    }
}

// round 10
// speedup vs baseline: 3.9042x; 1.1195x over previous
#include <cuda_runtime.h>
#include <cuda_fp16.h>
#include <math.h>
#include <stdint.h>

// Problem constants
#define Tn   2048
#define Hn   768
#define FFn  3072
#define Sn   256
#define Bn   8
#define NHn  12
#define HDn  64
#define NEn  4
#define Lnum 2

// Weight fp16 region offsets (in half2 units)
#define WQ_OFF  0
#define WK_OFF  589824
#define WV_OFF  1179648
#define W1_OFF  1769472
#define W2_OFF  11206656
#define W16_TOT 20643840

// ---------------- device scratch ----------------
__device__ float  g_x   [Tn * Hn];
__device__ __half g_h16 [Tn * Hn];
__device__ __half g_hg16[Tn * Hn];
__device__ float  g_q   [Tn * Hn];
__device__ float  g_k   [Tn * Hn];
__device__ float  g_v   [Tn * Hn];
__device__ float  g_x2  [Tn * Hn];
__device__ __half g_ffn16[(size_t)Tn * FFn];
__device__ float  g_part[3 * Tn * Hn];
__device__ __half g_w16 [2 * W16_TOT];
__device__ int    g_pos [Tn];
__device__ int    g_type[Tn];
__device__ int    g_ord [Tn];
__device__ int    g_inv [Tn];        // g_inv[pos[i]-1] = i ; -1 if unused
__device__ int    g_off [NEn + 1];

// x-buffer selectors (resolved in device code; host passes an int)
__device__ __forceinline__ const float* xsel(int s, const float* out) {
    return (s == 0) ? g_x : (s == 1) ? g_x2 : out;
}
__device__ __forceinline__ float* xsel_w(int s, float* out) {
    return (s == 0) ? g_x : (s == 1) ? g_x2 : out;
}

// ---------------- PTX helpers ----------------
__device__ __forceinline__ uint32_t su32(const void* p) {
    uint32_t a;
    asm("{ .reg .u64 t; cvta.to.shared.u64 t, %1; cvt.u32.u64 %0, t; }"
        : "=r"(a) : "l"(p));
    return a;
}
__device__ __forceinline__ void cpa16(uint32_t dst, const void* src) {
    asm volatile("cp.async.cg.shared.global [%0], [%1], 16;" :: "r"(dst), "l"(src));
}
__device__ __forceinline__ void cpa_commit() {
    asm volatile("cp.async.commit_group;" ::: "memory");
}
__device__ __forceinline__ void cpa_wait1() {
    asm volatile("cp.async.wait_group 1;" ::: "memory");
}
__device__ __forceinline__ void mma_f16(float* c, const uint32_t* a,
                                        uint32_t b0, uint32_t b1) {
    asm volatile(
        "mma.sync.aligned.m16n8k16.row.col.f32.f16.f16.f32 "
        "{%0,%1,%2,%3}, {%4,%5,%6,%7}, {%8,%9}, {%0,%1,%2,%3};"
        : "+f"(c[0]), "+f"(c[1]), "+f"(c[2]), "+f"(c[3])
        : "r"(a[0]), "r"(a[1]), "r"(a[2]), "r"(a[3]), "r"(b0), "r"(b1));
}

// ---------------- weight fp32 -> fp16, k-pair interleaved, coalesced ------
template<int K, int N>
__global__ void k_cvtw(const float* __restrict__ src, int dsth2) {
    int k2 = blockIdx.x;
    int m  = blockIdx.y;
    const float* s0 = src + ((size_t)m * K + 2 * k2) * N;
    const float* s1 = s0 + N;
    __half2* dst = ((__half2*)(void*)g_w16) + dsth2 + ((size_t)m * (K / 2) + k2) * N;
#pragma unroll
    for (int n = threadIdx.x * 4; n < N; n += blockDim.x * 4) {
        float4 a = *(const float4*)(s0 + n);
        float4 b = *(const float4*)(s1 + n);
        __half2 h0 = __floats2half2_rn(a.x, b.x);
        __half2 h1 = __floats2half2_rn(a.y, b.y);
        __half2 h2 = __floats2half2_rn(a.z, b.z);
        __half2 h3 = __floats2half2_rn(a.w, b.w);
        uint4 o;
        o.x = *(uint32_t*)&h0; o.y = *(uint32_t*)&h1;
        o.z = *(uint32_t*)&h2; o.w = *(uint32_t*)&h3;
        *(uint4*)(dst + n) = o;
    }
}

// ---------------- index prep (+ inverse permutation) ----------------
__global__ void k_prep(const void* __restrict__ pos, const void* __restrict__ typ) {
    __shared__ int s64p, s64t;
    if (threadIdx.x == 0) {
        const int* p32 = (const int*)pos;
        const int* t32 = (const int*)typ;
        int ap = 1, at = 1;
        for (int i = 1; i < 64; i += 2) { if (p32[i] != 0) { ap = 0; break; } }
        for (int i = 1; i < 64; i += 2) { if (t32[i] != 0) { at = 0; break; } }
        s64p = ap; s64t = at;
    }
    __syncthreads();
    for (int i = threadIdx.x; i < Tn; i += blockDim.x) {
        g_pos[i]  = s64p ? (int)((const long long*)pos)[i] : ((const int*)pos)[i];
        g_type[i] = s64t ? (int)((const long long*)typ)[i] : ((const int*)typ)[i];
        g_inv[i]  = -1;
    }
    __syncthreads();
    for (int i = threadIdx.x; i < Tn; i += blockDim.x) {
        int p = g_pos[i];
        if (p > 0) g_inv[p - 1] = i;
    }
}

// ---------------- expert routing ----------------
__global__ void k_route() {
    __shared__ int cnt[NEn], cur[NEn];
    int t = threadIdx.x;
    if (t < NEn) cnt[t] = 0;
    __syncthreads();
    for (int i = t; i < Tn; i += blockDim.x) atomicAdd(&cnt[g_type[i]], 1);
    __syncthreads();
    if (t == 0) {
        int run = 0;
        for (int e = 0; e < NEn; e++) { g_off[e] = run; cur[e] = run; run += cnt[e]; }
        g_off[NEn] = run;
    }
    __syncthreads();
    for (int i = t; i < Tn; i += blockDim.x) {
        int p = atomicAdd(&cur[g_type[i]], 1);
        g_ord[p] = i;
    }
}

// ---------------- x = input + sinusoidal PE ----------------
__global__ void k_add_pe(const float* __restrict__ xin) {
    int row = blockIdx.x;
    int s = row % Sn;
    const float c = -logf(10000.0f) / (float)Hn;
    for (int d = threadIdx.x; d < Hn; d += blockDim.x) {
        int i2 = d & ~1;
        float ang = (float)s * expf((float)i2 * c);
        float pe = (d & 1) ? cosf(ang) : sinf(ang);
        g_x[(size_t)row * Hn + d] = xin[(size_t)row * Hn + d] + pe;
    }
}

// ---------------- layernorm -> fp16 ----------------
__device__ __forceinline__ float warpSum(float v) {
#pragma unroll
    for (int o = 16; o > 0; o >>= 1) v += __shfl_down_sync(0xffffffffu, v, o);
    return v;
}
template<int GATHER>
__global__ void __launch_bounds__(192) k_ln(const float* __restrict__ w,
                                            const float* __restrict__ b,
                                            int xs) {
    const float* xsrc = xsel(xs, nullptr);
    int row = blockIdx.x;
    int rin = GATHER ? g_ord[row] : row;
    int t = threadIdx.x;
    float4 v = ((const float4*)(xsrc + (size_t)rin * Hn))[t];
    __shared__ float red[6];
    float s = warpSum(v.x + v.y + v.z + v.w);
    if ((t & 31) == 0) red[t >> 5] = s;
    __syncthreads();
    float mu = (red[0]+red[1]+red[2]+red[3]+red[4]+red[5]) * (1.0f / Hn);
    float4 d = make_float4(v.x - mu, v.y - mu, v.z - mu, v.w - mu);
    __syncthreads();
    s = warpSum(d.x*d.x + d.y*d.y + d.z*d.z + d.w*d.w);
    if ((t & 31) == 0) red[t >> 5] = s;
    __syncthreads();
    float var = (red[0]+red[1]+red[2]+red[3]+red[4]+red[5]) * (1.0f / Hn);
    float r = rsqrtf(var + 1e-5f);
    float4 wv = ((const float4*)w)[t];
    float4 bv = ((const float4*)b)[t];
    __half2* o = (__half2*)((GATHER ? g_hg16 : g_h16) + (size_t)row * Hn);
    o[t * 2]     = __floats2half2_rn(d.x * r * wv.x + bv.x, d.y * r * wv.y + bv.y);
    o[t * 2 + 1] = __floats2half2_rn(d.z * r * wv.z + bv.z, d.w * r * wv.w + bv.w);
}

// ---------------- fp16 mma GEMM (unchanged core) --------------------------
#define STG_U 6784

template<int MODE>
__global__ void __launch_bounds__(256) k_mm(int woff_l,
        const float* __restrict__ bq, const float* __restrict__ bk,
        const float* __restrict__ bv) {
    constexpr int N_    = (MODE == 1) ? FFn : Hn;
    constexpr int LDA2_ = (MODE == 2) ? (FFn / 2) : (Hn / 2);
    constexpr int NCH_  = (MODE == 2) ? 32 : 24;
    extern __shared__ uint32_t smu[];

    int z = blockIdx.z;
    int e = 0, sp = 0;
    int woff;
    const float* bias = nullptr;
    if (MODE == 0) {
        woff = woff_l + z * 589824;
        bias = (z == 0) ? bq : (z == 1) ? bk : bv;
    } else if (MODE == 1) {
        woff = woff_l + z * 1179648;
        bias = bq + z * FFn;
        e = z;
    } else {
        e = z & 3; sp = z >> 2;
        woff = woff_l + e * 1179648 + sp * 393216;
    }

    int M, rowbase;
    const __half2* A2;
    if (MODE == 0) { M = Tn; rowbase = 0; A2 = (const __half2*)(void*)g_h16; }
    else {
        rowbase = g_off[e];
        M = g_off[e + 1] - rowbase;
        A2 = (const __half2*)(void*)((MODE == 1) ? g_hg16 : g_ffn16);
    }
    int m0 = blockIdx.x * 128;
    if (m0 >= M) return;
    int n0 = blockIdx.y * 256;

    const __half2* W2g = ((const __half2*)(void*)g_w16) + woff;

    int tid = threadIdx.x;
    int wid = tid >> 5, lane = tid & 31;
    int gid = lane >> 2, tig = lane & 3;
    int wm = wid >> 2, wn = wid & 3;

    uint32_t smb = su32(smu);

    float acc[4][8][4];
#pragma unroll
    for (int i = 0; i < 4; i++)
#pragma unroll
        for (int j = 0; j < 8; j++)
#pragma unroll
            for (int q = 0; q < 4; q++) acc[i][j][q] = 0.f;

    auto load_chunk = [&](int ci, int st) {
        uint32_t sA = smb + (uint32_t)st * (STG_U * 4);
        uint32_t sB = sA + 2560u * 4u;
        int ak2 = ci * 16 + ((MODE == 2) ? sp * 512 : 0);
#pragma unroll
        for (int ii = 0; ii < 2; ii++) {
            int i = tid + ii * 256;
            int r = i >> 2, cq = (i & 3) * 4;
            int gr = rowbase + ((MODE == 0) ? (m0 + r) : min(m0 + r, M - 1));
            cpa16(sA + (uint32_t)(r * 20 + cq) * 4u,
                  A2 + (size_t)gr * LDA2_ + ak2 + cq);
        }
#pragma unroll
        for (int ii = 0; ii < 4; ii++) {
            int i = tid + ii * 256;
            int r = i >> 6, c = (i & 63) * 4;
            cpa16(sB + (uint32_t)(r * 264 + c) * 4u,
                  W2g + (size_t)(ci * 16 + r) * N_ + n0 + c);
        }
    };

    load_chunk(0, 0); cpa_commit();
    load_chunk(1, 1); cpa_commit();

    for (int i = 0; i < NCH_; i++) {
        cpa_wait1();
        __syncthreads();
        if (i + 2 < NCH_) load_chunk(i + 2, (i + 2) % 3);
        cpa_commit();

        const uint32_t* sAp = smu + (i % 3) * STG_U;
        const uint32_t* sBp = sAp + 2560;
#pragma unroll
        for (int kg = 0; kg < 2; kg++) {
            int kb2 = kg * 8;
            uint32_t a[4][4];
#pragma unroll
            for (int mi = 0; mi < 4; mi++) {
                int rm = wm * 64 + mi * 16 + gid;
                a[mi][0] = sAp[rm * 20 + kb2 + tig];
                a[mi][1] = sAp[(rm + 8) * 20 + kb2 + tig];
                a[mi][2] = sAp[rm * 20 + kb2 + tig + 4];
                a[mi][3] = sAp[(rm + 8) * 20 + kb2 + tig + 4];
            }
#pragma unroll
            for (int ni = 0; ni < 8; ni++) {
                int cn = wn * 64 + ni * 8 + gid;
                uint32_t b0 = sBp[(kb2 + tig) * 264 + cn];
                uint32_t b1 = sBp[(kb2 + tig + 4) * 264 + cn];
#pragma unroll
                for (int mi = 0; mi < 4; mi++)
                    mma_f16(acc[mi][ni], a[mi], b0, b1);
            }
        }
        __syncthreads();
    }

#pragma unroll
    for (int mi = 0; mi < 4; mi++) {
#pragma unroll
        for (int half = 0; half < 2; half++) {
            int rl = m0 + wm * 64 + mi * 16 + half * 8 + gid;
            if (rl >= M) continue;
#pragma unroll
            for (int ni = 0; ni < 8; ni++) {
                int col = n0 + wn * 64 + ni * 8 + tig * 2;
                float vx = acc[mi][ni][half * 2 + 0];
                float vy = acc[mi][ni][half * 2 + 1];
                if (MODE == 0) {
                    float2 bb = *(const float2*)(bias + col);
                    vx += bb.x; vy += bb.y;
                    float* Optr = (z == 0) ? g_q : (z == 1) ? g_k : g_v;
                    *(float2*)(Optr + (size_t)rl * Hn + col) = make_float2(vx, vy);
                } else if (MODE == 1) {
                    float2 bb = *(const float2*)(bias + col);
                    vx += bb.x; vy += bb.y;
                    vx = 0.5f * vx * (1.0f + erff(vx * 0.70710678118f));
                    vy = 0.5f * vy * (1.0f + erff(vy * 0.70710678118f));
                    int srow = rowbase + rl;
                    *(__half2*)(g_ffn16 + (size_t)srow * FFn + col) =
                        __floats2half2_rn(vx, vy);
                } else {
                    int srow = rowbase + rl;
                    *(float2*)(g_part + (size_t)sp * (Tn * Hn)
                               + (size_t)srow * Hn + col) = make_float2(vx, vy);
                }
            }
        }
    }
}

// ---------------- FFN2 finish: partials + bias + residual + direct scatter
__global__ void __launch_bounds__(192) k_fin(const float* __restrict__ b2l,
                                             int xs, int xd,
                                             float* __restrict__ outp) {
    const float* xsrc = xsel(xs, nullptr);
    float* xdst = xsel_w(xd, outp);
    int rs = blockIdx.x;
    int t = threadIdx.x;
    __shared__ int se, so;
    if (t == 0) {
        int e = 0;
        while (!(rs >= g_off[e] && rs < g_off[e + 1])) e++;
        se = e; so = g_ord[rs];
    }
    __syncthreads();
    int e = se, orow = so;
    int dr = g_inv[orow];
    if (dr >= 0) {
        float4 p0 = ((const float4*)(g_part + 0 * (Tn * Hn) + (size_t)rs * Hn))[t];
        float4 p1 = ((const float4*)(g_part + 1 * (Tn * Hn) + (size_t)rs * Hn))[t];
        float4 p2 = ((const float4*)(g_part + 2 * (Tn * Hn) + (size_t)rs * Hn))[t];
        float4 bb = ((const float4*)(b2l + (size_t)e * Hn))[t];
        float4 xr = ((const float4*)(xsrc + (size_t)orow * Hn))[t];
        float4 o;
        o.x = p0.x + p1.x + p2.x + bb.x + xr.x;
        o.y = p0.y + p1.y + p2.y + bb.y + xr.y;
        o.z = p0.z + p1.z + p2.z + bb.z + xr.z;
        o.w = p0.w + p1.w + p2.w + bb.w + xr.w;
        ((float4*)(xdst + (size_t)dr * Hn))[t] = o;
    }
    if (g_pos[rs] == 0)
        ((float4*)(xdst + (size_t)rs * Hn))[t] = make_float4(0.f, 0.f, 0.f, 0.f);
}

// ---------------- attention: block per (b,h,qchunk of 128), fp32 ----------
__global__ void __launch_bounds__(128) k_attn(int xs) {
    float* x = xsel_w(xs, nullptr);
    int b = blockIdx.x / NHn;
    int h = blockIdx.x % NHn;
    int t = blockIdx.y * 128 + threadIdx.x;
    int tid = threadIdx.x;
    const float* qp = g_q + ((size_t)(b * Sn + t)) * Hn + h * HDn;
    float qr[HDn];
#pragma unroll
    for (int d = 0; d < HDn; d += 4) {
        float4 v4 = *(const float4*)(qp + d);
        qr[d] = v4.x; qr[d+1] = v4.y; qr[d+2] = v4.z; qr[d+3] = v4.w;
    }
    float acc[HDn];
#pragma unroll
    for (int d = 0; d < HDn; d++) acc[d] = 0.f;
    float mx = -3.0e38f, lsum = 0.f;

    __shared__ __align__(16) float Ks[32][HDn];
    __shared__ __align__(16) float Vs[32][HDn];
    __shared__ float madd[32];

    for (int c = 0; c < Sn / 32; c++) {
        __syncthreads();
        for (int i = tid; i < 512; i += 128) {
            int j = i >> 4, d4 = (i & 15) * 4;
            size_t gi = ((size_t)(b * Sn + c * 32 + j)) * Hn + h * HDn + d4;
            *(float4*)&Ks[j][d4] = *(const float4*)(g_k + gi);
            *(float4*)&Vs[j][d4] = *(const float4*)(g_v + gi);
        }
        if (tid < 32) madd[tid] = (g_pos[b * Sn + c * 32 + tid] != 0) ? 0.f : -10000.0f;
        __syncthreads();

        float s[32];
        float cmx = -3.0e38f;
#pragma unroll
        for (int j = 0; j < 32; j++) {
            float dot = 0.f;
#pragma unroll
            for (int d = 0; d < HDn; d += 4) {
                float4 kv = *(const float4*)&Ks[j][d];
                dot += qr[d]*kv.x + qr[d+1]*kv.y + qr[d+2]*kv.z + qr[d+3]*kv.w;
            }
            s[j] = dot + madd[j];
            cmx = fmaxf(cmx, s[j]);
        }
        float nm = fmaxf(mx, cmx);
        float corr = expf(mx - nm);
        lsum *= corr;
#pragma unroll
        for (int d = 0; d < HDn; d++) acc[d] *= corr;
#pragma unroll
        for (int j = 0; j < 32; j++) {
            float p = expf(s[j] - nm);
            lsum += p;
#pragma unroll
            for (int d = 0; d < HDn; d += 4) {
                float4 vv = *(const float4*)&Vs[j][d];
                acc[d]   += p * vv.x; acc[d+1] += p * vv.y;
                acc[d+2] += p * vv.z; acc[d+3] += p * vv.w;
            }
        }
        mx = nm;
    }
    float inv = 1.0f / lsum;
    float* xp = x + ((size_t)(b * Sn + t)) * Hn + h * HDn;
#pragma unroll
    for (int d = 0; d < HDn; d++) xp[d] += acc[d] * inv;
}

// ---------------- launch ---------------------------------------------------
extern "C" void kernel_launch(void* const* d_in, const int* in_sizes, int n_in,
                              void* d_out, int out_size) {
    const float* x_in  = (const float*)d_in[0];
    const void*  npos  = d_in[1];
    const void*  ntype = d_in[2];
    const float* Wq  = (const float*)d_in[3];
    const float* bq  = (const float*)d_in[4];
    const float* Wk  = (const float*)d_in[5];
    const float* bk  = (const float*)d_in[6];
    const float* Wv  = (const float*)d_in[7];
    const float* bv  = (const float*)d_in[8];
    const float* ln1w = (const float*)d_in[9];
    const float* ln1b = (const float*)d_in[10];
    const float* ln2w = (const float*)d_in[11];
    const float* ln2b = (const float*)d_in[12];
    const float* W1 = (const float*)d_in[13];
    const float* b1 = (const float*)d_in[14];
    const float* W2 = (const float*)d_in[15];
    const float* b2 = (const float*)d_in[16];
    float* out = (float*)d_out;

    const int SMEM = 3 * STG_U * 4;   // 81408 B
    cudaFuncSetAttribute(k_mm<0>, cudaFuncAttributeMaxDynamicSharedMemorySize, SMEM);
    cudaFuncSetAttribute(k_mm<1>, cudaFuncAttributeMaxDynamicSharedMemorySize, SMEM);
    cudaFuncSetAttribute(k_mm<2>, cudaFuncAttributeMaxDynamicSharedMemorySize, SMEM);

    // Weight conversion (coalesced, templated shapes)
    k_cvtw<768, 768><<<dim3(384, 2), 192>>>(Wq, WQ_OFF);
    k_cvtw<768, 768><<<dim3(384, 2), 192>>>(Wk, WK_OFF);
    k_cvtw<768, 768><<<dim3(384, 2), 192>>>(Wv, WV_OFF);
    k_cvtw<768, 3072><<<dim3(384, 8), 256>>>(W1, W1_OFF);
    k_cvtw<3072, 768><<<dim3(1536, 8), 192>>>(W2, W2_OFF);

    k_prep<<<1, 256>>>(npos, ntype);
    k_route<<<1, 256>>>();
    k_add_pe<<<Tn, 256>>>(x_in);

    for (int l = 0; l < Lnum; l++) {
        int xs = (l == 0) ? 0 : 1;             // layer input: g_x then g_x2
        int xd = (l == Lnum - 1) ? 2 : 1;      // layer output: g_x2 then out

        k_ln<0><<<Tn, 192>>>(ln1w + l * Hn, ln1b + l * Hn, xs);

        k_mm<0><<<dim3(16, 3, 3), 256, SMEM>>>(
            l * 294912, bq + l * Hn, bk + l * Hn, bv + l * Hn);

        k_attn<<<dim3(Bn * NHn, Sn / 128), 128>>>(xs);

        k_ln<1><<<Tn, 192>>>(ln2w + l * Hn, ln2b + l * Hn, xs);

        k_mm<1><<<dim3(16, 12, 4), 256, SMEM>>>(
            W1_OFF + l * 4 * 1179648, b1 + (size_t)l * NEn * FFn, nullptr, nullptr);

        k_mm<2><<<dim3(16, 3, 12), 256, SMEM>>>(
            W2_OFF + l * 4 * 1179648, nullptr, nullptr, nullptr);

        k_fin<<<Tn, 192>>>(b2 + (size_t)l * NEn * Hn, xs, xd, out);
    }
}